// round 13
// baseline (speedup 1.0000x reference)
#include <cuda_runtime.h>
#include <cstdint>

// FPS + gather, bit-exact vs JAX/XLA (distance = fma(dz,dz, fma(dx,dx, rn(dy*dy)))).
// B=8, N=131072, S=4096.
//
// R12 = R10 flat skeleton (volatile tagged slots, single L2 hop, coord
// prefetch on detect) +
//  - f32x2 packed distance math (per-lane IEEE-identical; verified bit-exact
//    in R9, rel_err 0.0): fma-pipe load halves.
//  - own-slot self-detect: lane c marks its own slot got immediately (key is
//    locally known) -> straggler CTA no longer waits for its own store's
//    L2 round trip (the critical-path tail).
// Cluster machinery dropped (R11/R12 query always fell back; flat wins).

#define NB 8
#define NP 131072
#define NS 4096
#define CPB 16                 // CTAs per batch
#define NT 512                 // threads per CTA
#define ROUNDS (NS - 1)
#define PPC (NP / CPB)         // 8192 points per CTA

#define ADD2(r, a, b) asm("add.rn.f32x2 %0, %1, %2;" : "=l"(r) : "l"(a), "l"(b))
#define MUL2(r, a, b) asm("mul.rn.f32x2 %0, %1, %2;" : "=l"(r) : "l"(a), "l"(b))
#define FMA2(r, a, b, c) asm("fma.rn.f32x2 %0, %1, %2, %3;" : "=l"(r) : "l"(a), "l"(b), "l"(c))
#define PACK2(r, lo, hi) asm("mov.b64 %0, {%1, %2};" : "=l"(r) : "f"(lo), "f"(hi))
#define UNPACK2(lo, hi, r) asm("mov.b64 {%0, %1}, %2;" : "=f"(lo), "=f"(hi) : "l"(r))

__device__ float4 g_xyz[NB * NP];
struct __align__(2048) BSlots { unsigned long long key[CPB]; };
__device__ BSlots g_slots[NB];

__global__ void fps_prep_kernel(const float* __restrict__ pts) {
    if (blockIdx.x == 0 && threadIdx.x < NB * CPB) {
        g_slots[threadIdx.x / CPB].key[threadIdx.x % CPB] = 0ull;  // tag 0 < 1
    }
    int i = blockIdx.x * blockDim.x + threadIdx.x;
    int stride = gridDim.x * blockDim.x;
    for (; i < NB * NP; i += stride) {
        g_xyz[i] = make_float4(pts[3 * i + 0], pts[3 * i + 1], pts[3 * i + 2], 0.0f);
    }
}

__global__ void __launch_bounds__(NT, 1) fps_main_kernel(float* __restrict__ out) {
    const int b    = blockIdx.x / CPB;
    const int c    = blockIdx.x % CPB;
    const int tid  = threadIdx.x;
    const int lane = tid & 31;
    const int wid  = tid >> 5;
    const int base = c * PPC;
    const float4* __restrict__ P = g_xyz + b * NP;
    unsigned long long* __restrict__ slots = g_slots[b].key;

    // one-time: 16 points/thread -> 8 packed pairs per coordinate (R9 layout,
    // verified bit-exact)
    unsigned long long px2[8], py2[8], pz2[8];
    float md[16];
#pragma unroll
    for (int j = 0; j < 4; ++j) {
        const int e = j * NT + tid;
#pragma unroll
        for (int h = 0; h < 2; ++h) {
            float4 q0 = P[base + e * 4 + h * 2 + 0];
            float4 q1 = P[base + e * 4 + h * 2 + 1];
            PACK2(px2[j * 2 + h], q0.x, q1.x);
            PACK2(py2[j * 2 + h], q0.y, q1.y);
            PACK2(pz2[j * 2 + h], q0.z, q1.z);
        }
    }
#pragma unroll
    for (int i = 0; i < 16; ++i) md[i] = 1e10f;   // BIG

    __shared__ unsigned long long s_k[NT / 32];
    __shared__ float s_win[3];

    // selection 0 is always index 0
    float4 p0 = P[0];
    float lx = p0.x, ly = p0.y, lz = p0.z;
    if (c == 0 && tid == 0) {
        out[(b * NS + 0) * 3 + 0] = lx;
        out[(b * NS + 0) * 3 + 1] = ly;
        out[(b * NS + 0) * 3 + 2] = lz;
    }

    const int tb = base + tid * 4;

    for (int r = 0; r < ROUNDS; ++r) {
        float bestv = -1.0f;
        int   besti = 0;

        // packed negated last point (exact: a-b == a+(-b))
        unsigned long long nlx2, nly2, nlz2;
        { float nx = -lx, ny = -ly, nz = -lz;
          PACK2(nlx2, nx, nx); PACK2(nly2, ny, ny); PACK2(nlz2, nz, nz); }

#pragma unroll
        for (int p = 0; p < 8; ++p) {
            const int j = p >> 1, h = p & 1;
            const int idx0 = tb + j * (NT * 4) + h * 2;
            unsigned long long dx2, dy2, dz2, s2;
            // per-lane FROZEN sequence: dx=sub; dy=sub; dz=sub;
            // d = fma(dz,dz, fma(dx,dx, mul(dy,dy)))
            ADD2(dx2, px2[p], nlx2);
            ADD2(dy2, py2[p], nly2);
            ADD2(dz2, pz2[p], nlz2);
            MUL2(s2, dy2, dy2);
            FMA2(s2, dx2, dx2, s2);
            FMA2(s2, dz2, dz2, s2);
            float d0, d1;
            UNPACK2(d0, d1, s2);
            float m0 = fminf(md[p * 2 + 0], d0);
            md[p * 2 + 0] = m0;
            if (m0 > bestv) { bestv = m0; besti = idx0; }
            float m1 = fminf(md[p * 2 + 1], d1);
            md[p * 2 + 1] = m1;
            if (m1 > bestv) { bestv = m1; besti = idx0 + 1; }
        }

        // pack: max(key) == argmax(v) with min-idx tiebreak (v>=0 -> bits monotonic)
        unsigned long long wkey =
            ((unsigned long long)__float_as_uint(bestv) << 17) |
            (unsigned)(0x1FFFF - besti);

        // warp reduce (down: lane0 gets max)
#pragma unroll
        for (int off = 16; off > 0; off >>= 1) {
            unsigned long long ok = __shfl_down_sync(0xffffffffu, wkey, off);
            if (ok > wkey) wkey = ok;
        }
        if (lane == 0) s_k[wid] = wkey;
        __syncthreads();

        if (wid == 0) {
            const unsigned long long tag = (unsigned long long)(r + 1);  // 13 bits

            // CTA reduce over 16 warp keys (bfly: ALL lanes get kk, needed for
            // own-slot self-detect)
            unsigned long long kk = (lane < 16) ? s_k[lane] : 0ull;
#pragma unroll
            for (int off = 8; off > 0; off >>= 1) {
                unsigned long long ok = __shfl_xor_sync(0xffffffffu, kk, off);
                if (ok > kk) kk = ok;
            }
            if (lane == 0) {
                unsigned long long slot = (kk << 13) | tag;
                asm volatile("st.volatile.global.b64 [%0], %1;"
                             :: "l"(&slots[c]), "l"(slot) : "memory");
            }

            // single-hop: poll 16 slots (one lane each); own slot self-detects
            // (key locally known -> no L2 round trip for own store).
            unsigned long long k = 0ull;
            float4 w4 = make_float4(0.f, 0.f, 0.f, 0.f);
            bool got = (lane >= CPB);
            if (lane == c) {
                k = (kk << 13) | tag;
                got = true;
                w4 = P[0x1FFFF - (int)(kk & 0x1FFFFull)];   // own slice: L1 hit
            }
            do {
                if (!got) {
                    asm volatile("ld.volatile.global.b64 %0, [%1];"
                                 : "=l"(k) : "l"(&slots[lane]) : "memory");
                    if ((k & 0x1FFFull) == tag) {
                        got = true;
                        w4 = P[0x1FFFF - (int)((k >> 13) & 0x1FFFFull)];  // overlap
                    }
                }
            } while (!__all_sync(0xffffffffu, got));

            // cross-CTA reduce (bfly), then fetch winner coords by shuffle
            unsigned long long mykey = (lane < CPB) ? (k >> 13) : 0ull;
            unsigned long long k2 = mykey;
#pragma unroll
            for (int off = 8; off > 0; off >>= 1) {
                unsigned long long ok = __shfl_xor_sync(0xffffffffu, k2, off);
                if (ok > k2) k2 = ok;
            }
            unsigned wl = __ffs(__ballot_sync(0xffffffffu,
                                 (lane < CPB) && (mykey == k2))) - 1u;
            float wx = __shfl_sync(0xffffffffu, w4.x, wl);
            float wy = __shfl_sync(0xffffffffu, w4.y, wl);
            float wz = __shfl_sync(0xffffffffu, w4.z, wl);
            if (lane == 0) {
                s_win[0] = wx; s_win[1] = wy; s_win[2] = wz;
                if (c == 0) {
                    out[(b * NS + r + 1) * 3 + 0] = wx;
                    out[(b * NS + r + 1) * 3 + 1] = wy;
                    out[(b * NS + r + 1) * 3 + 2] = wz;
                }
            }
        }
        __syncthreads();
        lx = s_win[0]; ly = s_win[1]; lz = s_win[2];
    }
}

extern "C" void kernel_launch(void* const* d_in, const int* in_sizes, int n_in,
                              void* d_out, int out_size) {
    const float* pts = (const float*)d_in[0];
    float* out = (float*)d_out;
    (void)in_sizes; (void)n_in; (void)out_size;

    fps_prep_kernel<<<512, 256>>>(pts);
    fps_main_kernel<<<NB * CPB, NT>>>(out);
}